// round 2
// baseline (speedup 1.0000x reference)
#include <cuda_runtime.h>
#include <math.h>

// Problem dims (compile-time constants)
constexpr int NN   = 8192;  // nodes
constexpr int IND  = 512;   // input feature dim
constexpr int HIDD = 256;   // hidden dim
constexpr int OUTD = 128;   // output dim

// Scratch (allocation-free rule: __device__ globals)
__device__ __align__(128) float g_t1[NN * HIDD];   // feature @ W1
__device__ __align__(128) float g_h1[NN * HIDD];   // relu(adj @ t1 + b1)
__device__ __align__(128) float g_t2[NN * OUTD];   // h1 @ W2

enum { EPI_NONE = 0, EPI_BIAS = 1, EPI_BIAS_RELU = 2 };

__device__ __forceinline__ float sigmoidf_fast(float x) {
    // __expf(+inf) -> inf -> 1/(1+inf) = 0 ; __expf(-inf) -> 0 -> 1. Saturation-safe.
    return 1.0f / (1.0f + __expf(-x));
}

// ---------------------------------------------------------------------------
// Generic tiled fp32 GEMM: C[M,N] = epi(A[M,K] @ B[K,N] + bias)
// A row-major (lda=K), B row-major (ldb=N). All dims divisible by tile sizes.
// ---------------------------------------------------------------------------
template <int BM, int BN, int BK, int TM, int TN, int EPI>
__global__ __launch_bounds__((BM / TM) * (BN / TN))
void gemm_k(const float* __restrict__ A, const float* __restrict__ B,
            const float* __restrict__ bias, float* __restrict__ C,
            int M, int Ncols, int K)
{
    constexpr int THREADS = (BM / TM) * (BN / TN);
    __shared__ float As[BK][BM + 4];   // transposed A tile (pad kills bank conflicts)
    __shared__ float Bs[BK][BN];

    const int tid = threadIdx.x;
    const int tx  = tid % (BN / TN);
    const int ty  = tid / (BN / TN);
    const int rowBase = blockIdx.y * BM;
    const int colBase = blockIdx.x * BN;

    float acc[TM][TN];
#pragma unroll
    for (int i = 0; i < TM; i++)
#pragma unroll
        for (int j = 0; j < TN; j++) acc[i][j] = 0.0f;

    constexpr int A_F4 = BM * BK / 4;
    constexpr int A_IT = A_F4 / THREADS;
    static_assert(A_IT * THREADS == A_F4, "A tile load divisibility");
    constexpr int B_F4 = BK * BN / 4;
    constexpr int B_IT = B_F4 / THREADS;
    static_assert(B_IT * THREADS == B_F4, "B tile load divisibility");

    for (int k0 = 0; k0 < K; k0 += BK) {
        // Load A tile [BM x BK] -> transposed into As[k][m], float4 along K
#pragma unroll
        for (int i = 0; i < A_IT; i++) {
            int linear = tid + i * THREADS;
            int r  = linear / (BK / 4);
            int c4 = linear % (BK / 4);
            float4 v = *reinterpret_cast<const float4*>(
                &A[(rowBase + r) * K + k0 + c4 * 4]);
            As[c4 * 4 + 0][r] = v.x;
            As[c4 * 4 + 1][r] = v.y;
            As[c4 * 4 + 2][r] = v.z;
            As[c4 * 4 + 3][r] = v.w;
        }
        // Load B tile [BK x BN], float4 along N (coalesced, conflict-free)
#pragma unroll
        for (int i = 0; i < B_IT; i++) {
            int linear = tid + i * THREADS;
            int r  = linear / (BN / 4);
            int c4 = linear % (BN / 4);
            *reinterpret_cast<float4*>(&Bs[r][c4 * 4]) =
                *reinterpret_cast<const float4*>(&B[(k0 + r) * Ncols + colBase + c4 * 4]);
        }
        __syncthreads();

#pragma unroll
        for (int k = 0; k < BK; k++) {
            float ra[TM], rb[TN];
#pragma unroll
            for (int i = 0; i < TM; i += 4) {
                float4 v = *reinterpret_cast<const float4*>(&As[k][ty * TM + i]);
                ra[i] = v.x; ra[i + 1] = v.y; ra[i + 2] = v.z; ra[i + 3] = v.w;
            }
#pragma unroll
            for (int j = 0; j < TN; j += 4) {
                float4 v = *reinterpret_cast<const float4*>(&Bs[k][tx * TN + j]);
                rb[j] = v.x; rb[j + 1] = v.y; rb[j + 2] = v.z; rb[j + 3] = v.w;
            }
#pragma unroll
            for (int i = 0; i < TM; i++)
#pragma unroll
                for (int j = 0; j < TN; j++)
                    acc[i][j] = fmaf(ra[i], rb[j], acc[i][j]);
        }
        __syncthreads();
    }

    // Epilogue (float4 stores; all column offsets are multiples of 4)
#pragma unroll
    for (int i = 0; i < TM; i++) {
        int row = rowBase + ty * TM + i;
#pragma unroll
        for (int j = 0; j < TN; j += 4) {
            int col = colBase + tx * TN + j;
            float4 v;
            float c0 = acc[i][j + 0], c1 = acc[i][j + 1];
            float c2 = acc[i][j + 2], c3 = acc[i][j + 3];
            if (EPI == EPI_BIAS || EPI == EPI_BIAS_RELU) {
                c0 += bias[col + 0]; c1 += bias[col + 1];
                c2 += bias[col + 2]; c3 += bias[col + 3];
            }
            if (EPI == EPI_BIAS_RELU) {
                c0 = fmaxf(c0, 0.0f); c1 = fmaxf(c1, 0.0f);
                c2 = fmaxf(c2, 0.0f); c3 = fmaxf(c3, 0.0f);
            }
            v.x = c0; v.y = c1; v.z = c2; v.w = c3;
            *reinterpret_cast<float4*>(&C[row * Ncols + col]) = v;
        }
    }
}

// ---------------------------------------------------------------------------
// Decoder: out[i*NN + j] = sigmoid( dot(h[i,:], h[j,:]) ), h is [NN, OUTD]
// NT GEMM: both tiles load from h, K = OUTD = 128.
// ---------------------------------------------------------------------------
template <int BM, int BN, int BK, int TM, int TN>
__global__ __launch_bounds__((BM / TM) * (BN / TN))
void decoder_k(const float* __restrict__ h, float* __restrict__ out)
{
    constexpr int THREADS = (BM / TM) * (BN / TN);
    __shared__ float As[BK][BM + 4];
    __shared__ float Bs[BK][BN + 4];

    const int tid = threadIdx.x;
    const int tx  = tid % (BN / TN);
    const int ty  = tid / (BN / TN);
    const int rowBase = blockIdx.y * BM;
    const int colBase = blockIdx.x * BN;

    float acc[TM][TN];
#pragma unroll
    for (int i = 0; i < TM; i++)
#pragma unroll
        for (int j = 0; j < TN; j++) acc[i][j] = 0.0f;

    constexpr int T_F4 = BM * BK / 4;       // same for both tiles (BM==BN)
    constexpr int T_IT = T_F4 / THREADS;
    static_assert(T_IT * THREADS == T_F4, "tile load divisibility");

    for (int k0 = 0; k0 < OUTD; k0 += BK) {
        // Both operands are rows of h, loaded transposed (k-major smem)
#pragma unroll
        for (int i = 0; i < T_IT; i++) {
            int linear = tid + i * THREADS;
            int r  = linear / (BK / 4);
            int c4 = linear % (BK / 4);
            float4 va = *reinterpret_cast<const float4*>(
                &h[(rowBase + r) * OUTD + k0 + c4 * 4]);
            As[c4 * 4 + 0][r] = va.x;
            As[c4 * 4 + 1][r] = va.y;
            As[c4 * 4 + 2][r] = va.z;
            As[c4 * 4 + 3][r] = va.w;
            float4 vb = *reinterpret_cast<const float4*>(
                &h[(colBase + r) * OUTD + k0 + c4 * 4]);
            Bs[c4 * 4 + 0][r] = vb.x;
            Bs[c4 * 4 + 1][r] = vb.y;
            Bs[c4 * 4 + 2][r] = vb.z;
            Bs[c4 * 4 + 3][r] = vb.w;
        }
        __syncthreads();

#pragma unroll
        for (int k = 0; k < BK; k++) {
            float ra[TM], rb[TN];
#pragma unroll
            for (int i = 0; i < TM; i += 4) {
                float4 v = *reinterpret_cast<const float4*>(&As[k][ty * TM + i]);
                ra[i] = v.x; ra[i + 1] = v.y; ra[i + 2] = v.z; ra[i + 3] = v.w;
            }
#pragma unroll
            for (int j = 0; j < TN; j += 4) {
                float4 v = *reinterpret_cast<const float4*>(&Bs[k][tx * TN + j]);
                rb[j] = v.x; rb[j + 1] = v.y; rb[j + 2] = v.z; rb[j + 3] = v.w;
            }
#pragma unroll
            for (int i = 0; i < TM; i++)
#pragma unroll
                for (int j = 0; j < TN; j++)
                    acc[i][j] = fmaf(ra[i], rb[j], acc[i][j]);
        }
        __syncthreads();
    }

    // Sigmoid epilogue, float4 stores (268 MB total across grid)
#pragma unroll
    for (int i = 0; i < TM; i++) {
        int row = rowBase + ty * TM + i;
#pragma unroll
        for (int j = 0; j < TN; j += 4) {
            int col = colBase + tx * TN + j;
            float4 v;
            v.x = sigmoidf_fast(acc[i][j + 0]);
            v.y = sigmoidf_fast(acc[i][j + 1]);
            v.z = sigmoidf_fast(acc[i][j + 2]);
            v.w = sigmoidf_fast(acc[i][j + 3]);
            *reinterpret_cast<float4*>(&out[row * NN + col]) = v;
        }
    }
}

// ---------------------------------------------------------------------------
// Launch: adj, feature, W1, b1, W2, b2 -> out = [sigmoid(h@h.T) | h]
// ---------------------------------------------------------------------------
extern "C" void kernel_launch(void* const* d_in, const int* in_sizes, int n_in,
                              void* d_out, int out_size)
{
    const float* adj     = (const float*)d_in[0];
    const float* feature = (const float*)d_in[1];
    const float* W1      = (const float*)d_in[2];
    const float* b1      = (const float*)d_in[3];
    const float* W2      = (const float*)d_in[4];
    const float* b2      = (const float*)d_in[5];

    float* out   = (float*)d_out;                  // h_noise: NN*NN floats
    float* h_out = (float*)d_out + (size_t)NN * NN; // h: NN*OUTD floats

    float *t1p, *h1p, *t2p;
    cudaGetSymbolAddress((void**)&t1p, g_t1);
    cudaGetSymbolAddress((void**)&h1p, g_h1);
    cudaGetSymbolAddress((void**)&t2p, g_t2);

    // G1: t1 = feature @ W1           [8192,512]x[512,256]
    gemm_k<128, 64, 16, 8, 4, EPI_NONE>
        <<<dim3(HIDD / 64, NN / 128), 256>>>(feature, W1, nullptr, t1p, NN, HIDD, IND);

    // G2: h1 = relu(adj @ t1 + b1)    [8192,8192]x[8192,256]
    gemm_k<128, 64, 16, 8, 4, EPI_BIAS_RELU>
        <<<dim3(HIDD / 64, NN / 128), 256>>>(adj, t1p, b1, h1p, NN, HIDD, NN);

    // G3: t2 = h1 @ W2                [8192,256]x[256,128]
    gemm_k<128, 64, 16, 8, 4, EPI_NONE>
        <<<dim3(OUTD / 64, NN / 128), 256>>>(h1p, W2, nullptr, t2p, NN, OUTD, HIDD);

    // G4: h = adj @ t2 + b2           [8192,8192]x[8192,128] -> second output
    gemm_k<64, 64, 16, 4, 4, EPI_BIAS>
        <<<dim3(OUTD / 64, NN / 64), 256>>>(adj, t2p, b2, h_out, NN, OUTD, NN);

    // G5: out = sigmoid(h @ h.T)      [8192,128]x[128,8192]
    decoder_k<128, 128, 16, 8, 8>
        <<<dim3(NN / 128, NN / 128), 256>>>(h_out, out);
}

// round 8
// speedup vs baseline: 1.5772x; 1.5772x over previous
#include <cuda_runtime.h>
#include <cstdint>
#include <math.h>

constexpr int NN   = 8192;
constexpr int IND  = 512;
constexpr int HIDD = 256;
constexpr int OUTD = 128;

// Scratch (__device__ globals: allocation-free rule)
__device__ __align__(128) float g_t1T[HIDD * NN];          // (feature@W1)^T  [256,8192]
__device__ __align__(128) float g_h1 [NN * HIDD];          // relu(adj@t1+b1) [8192,256]
__device__ __align__(128) float g_t2T[OUTD * NN];          // (h1@W2)^T       [128,8192]
__device__ __align__(128) float g_part[4 * NN * OUTD];     // split-K partials (16 MB)

enum { EPI_NONE = 0, EPI_SIGMOID = 1 };

// ===========================================================================
// tf32 helpers (baseline PTX, sm_80+ — no tcgen05 / no 'a'-features)
// ===========================================================================
__device__ __forceinline__ uint32_t tf32_bits(float x) {
    uint32_t u;
    asm("cvt.rna.tf32.f32 %0, %1;" : "=r"(u) : "f"(x));
    return u;
}

__device__ __forceinline__ void mma_m16n8k8(float* c, const uint32_t* a, const uint32_t* b) {
    asm volatile(
        "mma.sync.aligned.m16n8k8.row.col.f32.tf32.tf32.f32 "
        "{%0,%1,%2,%3}, {%4,%5,%6,%7}, {%8,%9}, {%0,%1,%2,%3};"
        : "+f"(c[0]), "+f"(c[1]), "+f"(c[2]), "+f"(c[3])
        : "r"(a[0]), "r"(a[1]), "r"(a[2]), "r"(a[3]), "r"(b[0]), "r"(b[1]));
}

// ===========================================================================
// MUFU-free sigmoid (FFMA-only): exp2 poly + Newton reciprocal
// ===========================================================================
__device__ __forceinline__ float fast_sigmoid(float x) {
    const float L2E = 1.4426950408889634f;
    float ax = fabsf(x);
    float t  = fminf(ax * L2E, 126.0f);
    float u  = -t;
    float fi = floorf(u);
    float f  = u - fi;                   // [0,1)
    float p = 1.5252733804059838e-5f;
    p = fmaf(p, f, 1.5403530393381608e-4f);
    p = fmaf(p, f, 1.3333558146428443e-3f);
    p = fmaf(p, f, 9.6181291076284770e-3f);
    p = fmaf(p, f, 5.5504108664821580e-2f);
    p = fmaf(p, f, 2.4022650695910071e-1f);
    p = fmaf(p, f, 6.9314718055994531e-1f);
    p = fmaf(p, f, 1.0f);
    float scale = __int_as_float(((int)fi + 127) << 23);
    float e = p * scale;                 // exp(-|x|) in (0, 1]
    float d = 1.0f + e;
    float r = fmaf(e, fmaf(e, 0.3241f, -0.8104f), 0.9909f);
    r = r * fmaf(-d, r, 2.0f);
    r = r * fmaf(-d, r, 2.0f);
    return (x >= 0.0f) ? r : e * r;
}

// ===========================================================================
// tf32x3 tensor GEMM via mma.sync: C[128y,128x] = epi( A[M,K] @ B[N,K]^T )
// Both operands K-major. Split-K over blockIdx.z (partials at z*partStride).
// Smem: Ahi/Alo/Bhi/Blo, each [128 rows][36 floats] (pad -> conflict-free).
// ===========================================================================
constexpr int TS        = 36;                       // smem row stride (floats)
constexpr int TILE_FL   = 128 * TS;                 // floats per tile
constexpr int SMEM_DYN  = 4 * TILE_FL * 4;          // 73728 B

__device__ __forceinline__ void fill_tiles(
    const float* __restrict__ A, const float* __restrict__ B,
    float* __restrict__ sm, int rowBase, int colBase, int K, int k0, int tid)
{
    float* Ah = sm;
    float* Al = sm + TILE_FL;
    float* Bh = sm + 2 * TILE_FL;
    float* Bl = sm + 3 * TILE_FL;
#pragma unroll
    for (int it = 0; it < 8; ++it) {
        int linear = tid + it * 256;                // 0..2047
        const bool isA = (it < 4);
        int l  = isA ? linear : (linear - 1024);
        int r  = l >> 3;
        int c4 = l & 7;
        const float* gp = isA ? &A[(size_t)(rowBase + r) * K + k0 + c4 * 4]
                              : &B[(size_t)(colBase + r) * K + k0 + c4 * 4];
        float4 v = *reinterpret_cast<const float4*>(gp);
        float4 hi, lo;
        hi.x = __uint_as_float(tf32_bits(v.x)); lo.x = __uint_as_float(tf32_bits(v.x - hi.x));
        hi.y = __uint_as_float(tf32_bits(v.y)); lo.y = __uint_as_float(tf32_bits(v.y - hi.y));
        hi.z = __uint_as_float(tf32_bits(v.z)); lo.z = __uint_as_float(tf32_bits(v.z - hi.z));
        hi.w = __uint_as_float(tf32_bits(v.w)); lo.w = __uint_as_float(tf32_bits(v.w - hi.w));
        int off = r * TS + c4 * 4;
        *reinterpret_cast<float4*>((isA ? Ah : Bh) + off) = hi;
        *reinterpret_cast<float4*>((isA ? Al : Bl) + off) = lo;
    }
}

template <int EPI>
__global__ __launch_bounds__(256, 2)
void tgemm(const float* __restrict__ A, const float* __restrict__ B,
           float* __restrict__ C, int ldc, size_t partStride, int K, int kSplit)
{
    extern __shared__ __align__(16) float sm[];
    float* Ah = sm;
    float* Al = sm + TILE_FL;
    float* Bh = sm + 2 * TILE_FL;
    float* Bl = sm + 3 * TILE_FL;

    const int tid   = threadIdx.x;
    const int lane  = tid & 31;
    const int wid   = tid >> 5;
    const int warpM = wid & 1;          // 2 warp-rows (64 each)
    const int warpN = wid >> 1;         // 4 warp-cols (32 each)
    const int g     = lane >> 2;        // 0..7
    const int t     = lane & 3;         // 0..3

    const int rowBase = blockIdx.y * 128;
    const int colBase = blockIdx.x * 128;
    const int k0base  = blockIdx.z * kSplit;
    float* Cz = C + (size_t)blockIdx.z * partStride;
    const int KT = kSplit / 32;

    float acc[4][4][4];
#pragma unroll
    for (int i = 0; i < 4; i++)
#pragma unroll
        for (int j = 0; j < 4; j++)
#pragma unroll
            for (int q = 0; q < 4; q++) acc[i][j][q] = 0.0f;

    // Per-thread fragment base offsets (conflict-free: bank=(4g+t+c)%32 distinct)
    const int aBase = (warpM * 64 + g) * TS + t;
    const int bBase = (warpN * 32 + g) * TS + t;

    for (int kt = 0; kt < KT; ++kt) {
        fill_tiles(A, B, sm, rowBase, colBase, K, k0base + kt * 32, tid);
        __syncthreads();
#pragma unroll
        for (int k8 = 0; k8 < 4; ++k8) {
            const int kk = k8 * 8;
            uint32_t ah[4][4], bh[4][2];
#pragma unroll
            for (int mt = 0; mt < 4; mt++) {
                int o = aBase + mt * 16 * TS + kk;
                ah[mt][0] = __float_as_uint(Ah[o]);
                ah[mt][1] = __float_as_uint(Ah[o + 8 * TS]);
                ah[mt][2] = __float_as_uint(Ah[o + 4]);
                ah[mt][3] = __float_as_uint(Ah[o + 8 * TS + 4]);
            }
#pragma unroll
            for (int nt = 0; nt < 4; nt++) {
                int o = bBase + nt * 8 * TS + kk;
                bh[nt][0] = __float_as_uint(Bh[o]);
                bh[nt][1] = __float_as_uint(Bh[o + 4]);
            }
#pragma unroll
            for (int mt = 0; mt < 4; mt++)
#pragma unroll
                for (int nt = 0; nt < 4; nt++)
                    mma_m16n8k8(acc[mt][nt], ah[mt], bh[nt]);   // hi * hi

            {   // hi * lo  (B low part)
                uint32_t bl[4][2];
#pragma unroll
                for (int nt = 0; nt < 4; nt++) {
                    int o = bBase + nt * 8 * TS + kk;
                    bl[nt][0] = __float_as_uint(Bl[o]);
                    bl[nt][1] = __float_as_uint(Bl[o + 4]);
                }
#pragma unroll
                for (int mt = 0; mt < 4; mt++)
#pragma unroll
                    for (int nt = 0; nt < 4; nt++)
                        mma_m16n8k8(acc[mt][nt], ah[mt], bl[nt]);
            }
            {   // lo * hi  (A low part)
                uint32_t al[4][4];
#pragma unroll
                for (int mt = 0; mt < 4; mt++) {
                    int o = aBase + mt * 16 * TS + kk;
                    al[mt][0] = __float_as_uint(Al[o]);
                    al[mt][1] = __float_as_uint(Al[o + 8 * TS]);
                    al[mt][2] = __float_as_uint(Al[o + 4]);
                    al[mt][3] = __float_as_uint(Al[o + 8 * TS + 4]);
                }
#pragma unroll
                for (int mt = 0; mt < 4; mt++)
#pragma unroll
                    for (int nt = 0; nt < 4; nt++)
                        mma_m16n8k8(acc[mt][nt], al[mt], bh[nt]);
            }
        }
        __syncthreads();
    }

    // Epilogue: direct fragment stores (float2 -> full 32B sectors)
#pragma unroll
    for (int mt = 0; mt < 4; mt++) {
        const int row = rowBase + warpM * 64 + mt * 16 + g;
#pragma unroll
        for (int nt = 0; nt < 4; nt++) {
            const int col = colBase + warpN * 32 + nt * 8 + t * 2;
            float2 v0, v1;
            v0.x = acc[mt][nt][0]; v0.y = acc[mt][nt][1];   // row
            v1.x = acc[mt][nt][2]; v1.y = acc[mt][nt][3];   // row + 8
            if (EPI == EPI_SIGMOID) {
                v0.x = fast_sigmoid(v0.x); v0.y = fast_sigmoid(v0.y);
                v1.x = fast_sigmoid(v1.x); v1.y = fast_sigmoid(v1.y);
            }
            *reinterpret_cast<float2*>(&Cz[(size_t)row * ldc + col])       = v0;
            *reinterpret_cast<float2*>(&Cz[(size_t)(row + 8) * ldc + col]) = v1;
        }
    }
}

// ===========================================================================
// Split-K combine: out = sum_s p[s] + bias, optional relu
// ===========================================================================
template <int S, bool RELU>
__global__ void combine_k(const float* __restrict__ p, size_t stride,
                          const float* __restrict__ bias, float* __restrict__ o,
                          int ncols4)
{
    int i = blockIdx.x * blockDim.x + threadIdx.x;
    float4 a = reinterpret_cast<const float4*>(p)[i];
#pragma unroll
    for (int s = 1; s < S; s++) {
        float4 b = reinterpret_cast<const float4*>(p + (size_t)s * stride)[i];
        a.x += b.x; a.y += b.y; a.z += b.z; a.w += b.w;
    }
    float4 bb = reinterpret_cast<const float4*>(bias)[i % ncols4];
    a.x += bb.x; a.y += bb.y; a.z += bb.z; a.w += bb.w;
    if (RELU) {
        a.x = fmaxf(a.x, 0.0f); a.y = fmaxf(a.y, 0.0f);
        a.z = fmaxf(a.z, 0.0f); a.w = fmaxf(a.w, 0.0f);
    }
    reinterpret_cast<float4*>(o)[i] = a;
}

// ===========================================================================
// SIMT fp32 GEMM for the small layers (G1, G3); TRC = transposed store via
// smem staging (coalesced float4 column writes).
// ===========================================================================
template <int BM, int BN, int BK, int TM, int TN, bool TRC>
__global__ __launch_bounds__((BM / TM) * (BN / TN))
void gemm_k(const float* __restrict__ A, const float* __restrict__ B,
            float* __restrict__ C, int M, int Ncols, int K)
{
    constexpr int THREADS = (BM / TM) * (BN / TN);
    __shared__ float As[BK][BM + 4];
    __shared__ float Bs[BK][BN];
    __shared__ float Tr[TRC ? BN : 1][TRC ? (BM + 4) : 1];

    const int tid = threadIdx.x;
    const int tx  = tid % (BN / TN);
    const int ty  = tid / (BN / TN);
    const int rowBase = blockIdx.y * BM;
    const int colBase = blockIdx.x * BN;

    float acc[TM][TN];
#pragma unroll
    for (int i = 0; i < TM; i++)
#pragma unroll
        for (int j = 0; j < TN; j++) acc[i][j] = 0.0f;

    constexpr int A_IT = BM * BK / 4 / THREADS;
    constexpr int B_IT = BK * BN / 4 / THREADS;

    for (int k0 = 0; k0 < K; k0 += BK) {
#pragma unroll
        for (int i = 0; i < A_IT; i++) {
            int linear = tid + i * THREADS;
            int r = linear / (BK / 4), c4 = linear % (BK / 4);
            float4 v = *reinterpret_cast<const float4*>(&A[(size_t)(rowBase + r) * K + k0 + c4 * 4]);
            As[c4 * 4 + 0][r] = v.x; As[c4 * 4 + 1][r] = v.y;
            As[c4 * 4 + 2][r] = v.z; As[c4 * 4 + 3][r] = v.w;
        }
#pragma unroll
        for (int i = 0; i < B_IT; i++) {
            int linear = tid + i * THREADS;
            int r = linear / (BN / 4), c4 = linear % (BN / 4);
            *reinterpret_cast<float4*>(&Bs[r][c4 * 4]) =
                *reinterpret_cast<const float4*>(&B[(size_t)(k0 + r) * Ncols + colBase + c4 * 4]);
        }
        __syncthreads();
#pragma unroll
        for (int k = 0; k < BK; k++) {
            float ra[TM], rb[TN];
#pragma unroll
            for (int i = 0; i < TM; i += 4) {
                float4 v = *reinterpret_cast<const float4*>(&As[k][ty * TM + i]);
                ra[i] = v.x; ra[i + 1] = v.y; ra[i + 2] = v.z; ra[i + 3] = v.w;
            }
#pragma unroll
            for (int j = 0; j < TN; j += 4) {
                float4 v = *reinterpret_cast<const float4*>(&Bs[k][tx * TN + j]);
                rb[j] = v.x; rb[j + 1] = v.y; rb[j + 2] = v.z; rb[j + 3] = v.w;
            }
#pragma unroll
            for (int i = 0; i < TM; i++)
#pragma unroll
                for (int j = 0; j < TN; j++)
                    acc[i][j] = fmaf(ra[i], rb[j], acc[i][j]);
        }
        __syncthreads();
    }

    if (TRC) {
        // Stage transposed tile in smem, then coalesced column writes
#pragma unroll
        for (int i = 0; i < TM; i++)
#pragma unroll
            for (int j = 0; j < TN; j++)
                Tr[tx * TN + j][ty * TM + i] = acc[i][j];
        __syncthreads();
        constexpr int ST_IT = BM * BN / 4 / THREADS;
#pragma unroll
        for (int it = 0; it < ST_IT; it++) {
            int linear = tid + it * THREADS;
            int c  = linear / (BM / 4);
            int r4 = linear % (BM / 4);
            float4 v = *reinterpret_cast<const float4*>(&Tr[c][r4 * 4]);
            *reinterpret_cast<float4*>(&C[(size_t)(colBase + c) * M + rowBase + r4 * 4]) = v;
        }
    } else {
#pragma unroll
        for (int i = 0; i < TM; i++) {
            int row = rowBase + ty * TM + i;
#pragma unroll
            for (int j = 0; j < TN; j += 4) {
                int col = colBase + tx * TN + j;
                float4 v;
                v.x = acc[i][j]; v.y = acc[i][j + 1]; v.z = acc[i][j + 2]; v.w = acc[i][j + 3];
                *reinterpret_cast<float4*>(&C[(size_t)row * Ncols + col]) = v;
            }
        }
    }
}

// ===========================================================================
// Launch
// ===========================================================================
extern "C" void kernel_launch(void* const* d_in, const int* in_sizes, int n_in,
                              void* d_out, int out_size)
{
    const float* adj     = (const float*)d_in[0];
    const float* feature = (const float*)d_in[1];
    const float* W1      = (const float*)d_in[2];
    const float* b1      = (const float*)d_in[3];
    const float* W2      = (const float*)d_in[4];
    const float* b2      = (const float*)d_in[5];

    float* out   = (float*)d_out;                    // sigmoid(h@h^T): NN*NN
    float* h_out = (float*)d_out + (size_t)NN * NN;  // h: NN*OUTD

    float *t1T, *h1, *t2T, *part;
    cudaGetSymbolAddress((void**)&t1T,  g_t1T);
    cudaGetSymbolAddress((void**)&h1,   g_h1);
    cudaGetSymbolAddress((void**)&t2T,  g_t2T);
    cudaGetSymbolAddress((void**)&part, g_part);

    cudaFuncSetAttribute((const void*)tgemm<EPI_NONE>,
                         cudaFuncAttributeMaxDynamicSharedMemorySize, SMEM_DYN);
    cudaFuncSetAttribute((const void*)tgemm<EPI_SIGMOID>,
                         cudaFuncAttributeMaxDynamicSharedMemorySize, SMEM_DYN);

    // G1 (SIMT): t1T = (feature @ W1)^T          [8192,512]x[512,256]
    gemm_k<128, 64, 16, 8, 4, true>
        <<<dim3(HIDD / 64, NN / 128), 256>>>(feature, W1, t1T, NN, HIDD, IND);

    // G2 (mma, split-K=2): partials of adj @ t1T^T   [8192,8192]x[256,8192]^T
    tgemm<EPI_NONE><<<dim3(HIDD / 128, NN / 128, 2), 256, SMEM_DYN>>>(
        adj, t1T, part, HIDD, (size_t)NN * HIDD, NN, NN / 2);

    // Combine: h1 = relu(p0 + p1 + b1)
    combine_k<2, true><<<(NN * HIDD / 4) / 256, 256>>>(
        part, (size_t)NN * HIDD, b1, h1, HIDD / 4);

    // G3 (SIMT): t2T = (h1 @ W2)^T               [8192,256]x[256,128]
    gemm_k<128, 64, 16, 8, 4, true>
        <<<dim3(OUTD / 64, NN / 128), 256>>>(h1, W2, t2T, NN, OUTD, HIDD);

    // G4 (mma, split-K=4): partials of adj @ t2T^T
    tgemm<EPI_NONE><<<dim3(OUTD / 128, NN / 128, 4), 256, SMEM_DYN>>>(
        adj, t2T, part, OUTD, (size_t)NN * OUTD, NN, NN / 4);

    // Combine: h = p0 + p1 + p2 + p3 + b2
    combine_k<4, false><<<(NN * OUTD / 4) / 256, 256>>>(
        part, (size_t)NN * OUTD, b2, h_out, OUTD / 4);

    // G5 (mma): out = sigmoid(h @ h^T)           [8192,128]x[8192,128]^T
    tgemm<EPI_SIGMOID><<<dim3(NN / 128, NN / 128, 1), 256, SMEM_DYN>>>(
        h_out, h_out, out, NN, 0, OUTD, OUTD);
}

// round 9
// speedup vs baseline: 2.8877x; 1.8309x over previous
#include <cuda_runtime.h>
#include <cstdint>
#include <math.h>

constexpr int NN   = 8192;
constexpr int IND  = 512;
constexpr int HIDD = 256;
constexpr int OUTD = 128;

// bf16 tile geometry: 128 rows x 32 k-elems, rows padded to 20 words (80B)
constexpr int TKW     = 20;             // words per row (16 data + 4 pad)
constexpr int TILE_W  = 128 * TKW;      // 2560 words per tile
constexpr int STAGE_W = 4 * TILE_W;     // Ahi, Alo, Bhi, Blo
constexpr int SMEM_DYN = 2 * STAGE_W * 4;   // 81920 B (double-buffered)

// Scratch (__device__ globals: allocation-free rule)
__device__ __align__(128) float    g_h1 [NN * HIDD];             // relu layer-1 out
__device__ __align__(128) float    g_part[4 * NN * OUTD];        // split-K partials
// Pre-split bf16 B-operands in smem-image tile layout (hi/lo pairs)
__device__ __align__(128) uint32_t g_B1hi[(size_t)2 * 256 * TILE_W];
__device__ __align__(128) uint32_t g_B1lo[(size_t)2 * 256 * TILE_W];
__device__ __align__(128) uint32_t g_B2hi[(size_t)1 * 256 * TILE_W];
__device__ __align__(128) uint32_t g_B2lo[(size_t)1 * 256 * TILE_W];
__device__ __align__(128) uint32_t g_Bhhi[(size_t)64 * 4 * TILE_W];
__device__ __align__(128) uint32_t g_Bhlo[(size_t)64 * 4 * TILE_W];

enum { EPI_NONE = 0, EPI_SIGMOID = 1 };

// ===========================================================================
// Helpers (all baseline sm_80+ PTX — compiles under compute_103)
// ===========================================================================
__device__ __forceinline__ uint32_t smem_u32(const void* p) {
    uint32_t a;
    asm("{ .reg .u64 t; cvta.to.shared.u64 t, %1; cvt.u32.u64 %0, t; }" : "=r"(a) : "l"(p));
    return a;
}
// pack: d[31:16]=bf16(hiElem), d[15:0]=bf16(loElem)
__device__ __forceinline__ uint32_t pack_bf(float odd, float even) {
    uint32_t r;
    asm("cvt.rn.bf16x2.f32 %0, %1, %2;" : "=r"(r) : "f"(odd), "f"(even));
    return r;
}
__device__ __forceinline__ float bf_lo(uint32_t w) { return __uint_as_float(w << 16); }
__device__ __forceinline__ float bf_hi(uint32_t w) { return __uint_as_float(w & 0xffff0000u); }

__device__ __forceinline__ void mma_bf16(float* c, const uint32_t* a, const uint32_t* b) {
    asm volatile(
        "mma.sync.aligned.m16n8k16.row.col.f32.bf16.bf16.f32 "
        "{%0,%1,%2,%3}, {%4,%5,%6,%7}, {%8,%9}, {%0,%1,%2,%3};"
        : "+f"(c[0]), "+f"(c[1]), "+f"(c[2]), "+f"(c[3])
        : "r"(a[0]), "r"(a[1]), "r"(a[2]), "r"(a[3]), "r"(b[0]), "r"(b[1]));
}
__device__ __forceinline__ void cpasync16(uint32_t dst, const void* src) {
    asm volatile("cp.async.ca.shared.global [%0], [%1], 16;" :: "r"(dst), "l"(src) : "memory");
}
__device__ __forceinline__ void cpwait_all() {
    asm volatile("cp.async.wait_all;" ::: "memory");
}

// Split fp32 x -> (hiWordPair, loWordPair) for 4 consecutive elems
__device__ __forceinline__ void split4(float4 v, uint2& h, uint2& l) {
    h.x = pack_bf(v.y, v.x);
    h.y = pack_bf(v.w, v.z);
    l.x = pack_bf(v.y - bf_hi(h.x), v.x - bf_lo(h.x));
    l.y = pack_bf(v.w - bf_hi(h.y), v.z - bf_lo(h.y));
}

// B-frag global word offset for element (n, k); KTt = K/32
__device__ __forceinline__ size_t bfrag_off(int n, int k0, int KTt) {
    return ((size_t)(n >> 7) * KTt + (k0 >> 5)) * TILE_W
         + (size_t)(n & 127) * TKW + ((k0 & 31) >> 1);
}

// MUFU-free sigmoid (FFMA-only)
__device__ __forceinline__ float fast_sigmoid(float x) {
    const float L2E = 1.4426950408889634f;
    float ax = fabsf(x);
    float t  = fminf(ax * L2E, 126.0f);
    float u  = -t;
    float fi = floorf(u);
    float f  = u - fi;
    float p = 1.5252733804059838e-5f;
    p = fmaf(p, f, 1.5403530393381608e-4f);
    p = fmaf(p, f, 1.3333558146428443e-3f);
    p = fmaf(p, f, 9.6181291076284770e-3f);
    p = fmaf(p, f, 5.5504108664821580e-2f);
    p = fmaf(p, f, 2.4022650695910071e-1f);
    p = fmaf(p, f, 6.9314718055994531e-1f);
    p = fmaf(p, f, 1.0f);
    float scale = __int_as_float(((int)fi + 127) << 23);
    float e = p * scale;
    float d = 1.0f + e;
    float r = fmaf(e, fmaf(e, 0.3241f, -0.8104f), 0.9909f);
    r = r * fmaf(-d, r, 2.0f);
    r = r * fmaf(-d, r, 2.0f);
    return (x >= 0.0f) ? r : e * r;
}

// ===========================================================================
// bf16x3 tensor GEMM: C[128y,128x] = epi( A[M,K] @ B[N,K]^T )
// A fp32 K-major (converted in-kernel); B pre-split bf16 hi/lo tile arrays.
// Double-buffered smem, LDG prefetch, cp.async B fill, 1 sync per k-tile.
// ===========================================================================
template <int EPI>
__global__ __launch_bounds__(256, 2)
void tgemm(const float* __restrict__ A,
           const uint32_t* __restrict__ Bhi, const uint32_t* __restrict__ Blo,
           float* __restrict__ C, int ldc, size_t partStride, int K, int kSplit)
{
    extern __shared__ __align__(16) uint32_t sm[];
    const int tid  = threadIdx.x;
    const int lane = tid & 31;
    const int wid  = tid >> 5;
    const int warpM = wid & 1;          // 2 warp-rows of 64
    const int warpN = wid >> 1;         // 4 warp-cols of 32
    const int g = lane >> 2;
    const int t = lane & 3;

    const int rowBase = blockIdx.y * 128;
    const int colBase = blockIdx.x * 128;
    const int KTtot   = K >> 5;
    const int KT      = kSplit >> 5;
    const int kt0     = blockIdx.z * KT;
    float* Cz = C + (size_t)blockIdx.z * partStride;
    const uint32_t sbase = smem_u32(sm);

    float acc[4][4][4];
#pragma unroll
    for (int i = 0; i < 4; i++)
#pragma unroll
        for (int j = 0; j < 4; j++)
#pragma unroll
            for (int q = 0; q < 4; q++) acc[i][j][q] = 0.0f;

    // ---- fill primitives ----
    auto ldgA = [&](int kt, float4* pf) {
        const int k0 = (kt0 + kt) << 5;
#pragma unroll
        for (int i = 0; i < 4; i++) {
            int l = tid + i * 256, r = l >> 3, c4 = l & 7;
            pf[i] = *reinterpret_cast<const float4*>(
                &A[(size_t)(rowBase + r) * K + k0 + c4 * 4]);
        }
    };
    auto stsA = [&](int s, const float4* pf) {
        uint32_t* Ah = sm + s * STAGE_W;
        uint32_t* Al = Ah + TILE_W;
#pragma unroll
        for (int i = 0; i < 4; i++) {
            int l = tid + i * 256, r = l >> 3, c4 = l & 7;
            uint2 h, lo;
            split4(pf[i], h, lo);
            int w = r * TKW + c4 * 2;
            *reinterpret_cast<uint2*>(&Ah[w]) = h;
            *reinterpret_cast<uint2*>(&Al[w]) = lo;
        }
    };
    auto cpB = [&](int kt, int s) {
        size_t tile = ((size_t)blockIdx.x * KTtot + (kt0 + kt)) * (size_t)TILE_W;
        uint32_t dB = sbase + (uint32_t)(s * STAGE_W + 2 * TILE_W) * 4;
        const char* sh = (const char*)(Bhi + tile);
        const char* sl = (const char*)(Blo + tile);
#pragma unroll
        for (int i = 0; i < 5; i++) {
            int c = tid + i * 256;                // 1280 x 16B chunks (hi+lo)
            if (c < 640) cpasync16(dB + c * 16, sh + (size_t)c * 16);
            else cpasync16(dB + TILE_W * 4 + (c - 640) * 16, sl + (size_t)(c - 640) * 16);
        }
    };

    // Prologue: stage 0
    {
        float4 pf[4];
        ldgA(0, pf);
        stsA(0, pf);
        cpB(0, 0);
    }

    float4 pf[4];
    for (int kt = 0; kt < KT; ++kt) {
        cpwait_all();
        __syncthreads();                  // stage cur complete; stage nxt free
        const int cur = kt & 1;
        const bool more = (kt + 1 < KT);
        if (more) ldgA(kt + 1, pf);       // overlap gmem with mma

        const uint32_t* Ah = sm + cur * STAGE_W;
        const uint32_t* Al = Ah + TILE_W;
        const uint32_t* Bh = Ah + 2 * TILE_W;
        const uint32_t* Bl = Ah + 3 * TILE_W;

#pragma unroll
        for (int s8 = 0; s8 < 2; s8++) {  // two k16 steps per 32-k tile
            uint32_t bh[4][2], bl[4][2];
#pragma unroll
            for (int nt = 0; nt < 4; nt++) {
                int o = (warpN * 32 + nt * 8 + g) * TKW + s8 * 8 + t;
                bh[nt][0] = Bh[o]; bh[nt][1] = Bh[o + 4];
                bl[nt][0] = Bl[o]; bl[nt][1] = Bl[o + 4];
            }
#pragma unroll
            for (int mt = 0; mt < 4; mt++) {
                int o = (warpM * 64 + mt * 16 + g) * TKW + s8 * 8 + t;
                uint32_t ah[4] = {Ah[o], Ah[o + 8 * TKW], Ah[o + 4], Ah[o + 8 * TKW + 4]};
                uint32_t al[4] = {Al[o], Al[o + 8 * TKW], Al[o + 4], Al[o + 8 * TKW + 4]};
#pragma unroll
                for (int nt = 0; nt < 4; nt++) {
                    mma_bf16(acc[mt][nt], ah, bh[nt]);   // hi*hi
                    mma_bf16(acc[mt][nt], ah, bl[nt]);   // hi*lo
                    mma_bf16(acc[mt][nt], al, bh[nt]);   // lo*hi
                }
            }
        }
        if (more) {
            stsA(cur ^ 1, pf);
            cpB(kt + 1, cur ^ 1);
        }
    }

    // Epilogue: direct fragment stores (float2)
#pragma unroll
    for (int mt = 0; mt < 4; mt++) {
        const int row = rowBase + warpM * 64 + mt * 16 + g;
#pragma unroll
        for (int nt = 0; nt < 4; nt++) {
            const int col = colBase + warpN * 32 + nt * 8 + t * 2;
            float2 v0, v1;
            v0.x = acc[mt][nt][0]; v0.y = acc[mt][nt][1];
            v1.x = acc[mt][nt][2]; v1.y = acc[mt][nt][3];
            if (EPI == EPI_SIGMOID) {
                v0.x = fast_sigmoid(v0.x); v0.y = fast_sigmoid(v0.y);
                v1.x = fast_sigmoid(v1.x); v1.y = fast_sigmoid(v1.y);
            }
            *reinterpret_cast<float2*>(&Cz[(size_t)row * ldc + col])       = v0;
            *reinterpret_cast<float2*>(&Cz[(size_t)(row + 8) * ldc + col]) = v1;
        }
    }
}

// ===========================================================================
// Split-K combine: out = sum_s p[s] + bias (+relu); optionally also emit
// bf16 hi/lo B-frag copy (for h -> G5 operand).
// ===========================================================================
template <int S, bool RELU, bool FRAG>
__global__ void combine_k(const float* __restrict__ p, size_t stride,
                          const float* __restrict__ bias, float* __restrict__ o,
                          int ncols4, uint32_t* __restrict__ fhi, uint32_t* __restrict__ flo)
{
    int i = blockIdx.x * blockDim.x + threadIdx.x;
    float4 a = reinterpret_cast<const float4*>(p)[i];
#pragma unroll
    for (int s = 1; s < S; s++) {
        float4 b = reinterpret_cast<const float4*>(p + (size_t)s * stride)[i];
        a.x += b.x; a.y += b.y; a.z += b.z; a.w += b.w;
    }
    float4 bb = reinterpret_cast<const float4*>(bias)[i % ncols4];
    a.x += bb.x; a.y += bb.y; a.z += bb.z; a.w += bb.w;
    if (RELU) {
        a.x = fmaxf(a.x, 0.0f); a.y = fmaxf(a.y, 0.0f);
        a.z = fmaxf(a.z, 0.0f); a.w = fmaxf(a.w, 0.0f);
    }
    reinterpret_cast<float4*>(o)[i] = a;
    if (FRAG) {
        int j  = i >> 5;              // row (OUTD=128 -> 32 float4/row)
        int k0 = (i & 31) * 4;
        uint2 h, l;
        split4(a, h, l);
        size_t w = bfrag_off(j, k0, OUTD / 32);
        *reinterpret_cast<uint2*>(&fhi[w]) = h;
        *reinterpret_cast<uint2*>(&flo[w]) = l;
    }
}

// ===========================================================================
// SIMT fp32 GEMM (G1, G3): computes A@B then stores bf16 hi/lo B-frag layout
// (n = output col, k = output row) via smem-staged transpose.
// ===========================================================================
template <int BM, int BN, int BK, int TM, int TN>
__global__ __launch_bounds__((BM / TM) * (BN / TN))
void gemm_frag_k(const float* __restrict__ A, const float* __restrict__ B,
                 uint32_t* __restrict__ fhi, uint32_t* __restrict__ flo,
                 int M, int Ncols, int K)
{
    constexpr int THREADS = (BM / TM) * (BN / TN);
    __shared__ float As[BK][BM + 4];
    __shared__ float Bs[BK][BN];
    __shared__ float Tr[BN][BM + 4];

    const int tid = threadIdx.x;
    const int tx  = tid % (BN / TN);
    const int ty  = tid / (BN / TN);
    const int rowBase = blockIdx.y * BM;
    const int colBase = blockIdx.x * BN;

    float acc[TM][TN];
#pragma unroll
    for (int i = 0; i < TM; i++)
#pragma unroll
        for (int j = 0; j < TN; j++) acc[i][j] = 0.0f;

    constexpr int A_IT = BM * BK / 4 / THREADS;
    constexpr int B_IT = BK * BN / 4 / THREADS;

    for (int k0 = 0; k0 < K; k0 += BK) {
#pragma unroll
        for (int i = 0; i < A_IT; i++) {
            int linear = tid + i * THREADS;
            int r = linear / (BK / 4), c4 = linear % (BK / 4);
            float4 v = *reinterpret_cast<const float4*>(&A[(size_t)(rowBase + r) * K + k0 + c4 * 4]);
            As[c4 * 4 + 0][r] = v.x; As[c4 * 4 + 1][r] = v.y;
            As[c4 * 4 + 2][r] = v.z; As[c4 * 4 + 3][r] = v.w;
        }
#pragma unroll
        for (int i = 0; i < B_IT; i++) {
            int linear = tid + i * THREADS;
            int r = linear / (BN / 4), c4 = linear % (BN / 4);
            *reinterpret_cast<float4*>(&Bs[r][c4 * 4]) =
                *reinterpret_cast<const float4*>(&B[(size_t)(k0 + r) * Ncols + colBase + c4 * 4]);
        }
        __syncthreads();
#pragma unroll
        for (int k = 0; k < BK; k++) {
            float ra[TM], rb[TN];
#pragma unroll
            for (int i = 0; i < TM; i += 4) {
                float4 v = *reinterpret_cast<const float4*>(&As[k][ty * TM + i]);
                ra[i] = v.x; ra[i + 1] = v.y; ra[i + 2] = v.z; ra[i + 3] = v.w;
            }
#pragma unroll
            for (int j = 0; j < TN; j += 4) {
                float4 v = *reinterpret_cast<const float4*>(&Bs[k][tx * TN + j]);
                rb[j] = v.x; rb[j + 1] = v.y; rb[j + 2] = v.z; rb[j + 3] = v.w;
            }
#pragma unroll
            for (int i = 0; i < TM; i++)
#pragma unroll
                for (int j = 0; j < TN; j++)
                    acc[i][j] = fmaf(ra[i], rb[j], acc[i][j]);
        }
        __syncthreads();
    }

    // Stage transposed (Tr[n][k]) then emit bf16 hi/lo frag tiles
#pragma unroll
    for (int i = 0; i < TM; i++)
#pragma unroll
        for (int j = 0; j < TN; j++)
            Tr[tx * TN + j][ty * TM + i] = acc[i][j];
    __syncthreads();

    const int KTt = M / 32;
    constexpr int ST_IT = BM * BN / 4 / THREADS;
#pragma unroll
    for (int it = 0; it < ST_IT; it++) {
        int linear = tid + it * THREADS;
        int c  = linear / (BM / 4);
        int r4 = linear % (BM / 4);
        float4 v = *reinterpret_cast<const float4*>(&Tr[c][r4 * 4]);
        uint2 h, l;
        split4(v, h, l);
        int n  = colBase + c;
        int k0 = rowBase + r4 * 4;
        size_t w = bfrag_off(n, k0, KTt);
        *reinterpret_cast<uint2*>(&fhi[w]) = h;
        *reinterpret_cast<uint2*>(&flo[w]) = l;
    }
}

// ===========================================================================
// Launch
// ===========================================================================
extern "C" void kernel_launch(void* const* d_in, const int* in_sizes, int n_in,
                              void* d_out, int out_size)
{
    const float* adj     = (const float*)d_in[0];
    const float* feature = (const float*)d_in[1];
    const float* W1      = (const float*)d_in[2];
    const float* b1      = (const float*)d_in[3];
    const float* W2      = (const float*)d_in[4];
    const float* b2      = (const float*)d_in[5];

    float* out   = (float*)d_out;                    // sigmoid(h@h^T): NN*NN
    float* h_out = (float*)d_out + (size_t)NN * NN;  // h: NN*OUTD

    float *h1, *part;
    uint32_t *B1hi, *B1lo, *B2hi, *B2lo, *Bhhi, *Bhlo;
    cudaGetSymbolAddress((void**)&h1,   g_h1);
    cudaGetSymbolAddress((void**)&part, g_part);
    cudaGetSymbolAddress((void**)&B1hi, g_B1hi);
    cudaGetSymbolAddress((void**)&B1lo, g_B1lo);
    cudaGetSymbolAddress((void**)&B2hi, g_B2hi);
    cudaGetSymbolAddress((void**)&B2lo, g_B2lo);
    cudaGetSymbolAddress((void**)&Bhhi, g_Bhhi);
    cudaGetSymbolAddress((void**)&Bhlo, g_Bhlo);

    cudaFuncSetAttribute((const void*)tgemm<EPI_NONE>,
                         cudaFuncAttributeMaxDynamicSharedMemorySize, SMEM_DYN);
    cudaFuncSetAttribute((const void*)tgemm<EPI_SIGMOID>,
                         cudaFuncAttributeMaxDynamicSharedMemorySize, SMEM_DYN);

    // G1: t1 = feature @ W1 -> bf16 hi/lo B-frag (n=256, K=8192 tile layout)
    gemm_frag_k<128, 64, 16, 8, 4>
        <<<dim3(HIDD / 64, NN / 128), 256>>>(feature, W1, B1hi, B1lo, NN, HIDD, IND);

    // G2: partials of adj @ t1^T  (split-K=2)
    tgemm<EPI_NONE><<<dim3(HIDD / 128, NN / 128, 2), 256, SMEM_DYN>>>(
        adj, B1hi, B1lo, part, HIDD, (size_t)NN * HIDD, NN, NN / 2);

    // h1 = relu(p0 + p1 + b1)
    combine_k<2, true, false><<<(NN * HIDD / 4) / 256, 256>>>(
        part, (size_t)NN * HIDD, b1, h1, HIDD / 4, nullptr, nullptr);

    // G3: t2 = h1 @ W2 -> bf16 hi/lo B-frag (n=128, K=8192)
    gemm_frag_k<128, 64, 16, 8, 4>
        <<<dim3(OUTD / 64, NN / 128), 256>>>(h1, W2, B2hi, B2lo, NN, OUTD, HIDD);

    // G4: partials of adj @ t2^T  (split-K=4)
    tgemm<EPI_NONE><<<dim3(OUTD / 128, NN / 128, 4), 256, SMEM_DYN>>>(
        adj, B2hi, B2lo, part, OUTD, (size_t)NN * OUTD, NN, NN / 4);

    // h = p0+p1+p2+p3 + b2  (also emits h bf16 B-frag for G5)
    combine_k<4, false, true><<<(NN * OUTD / 4) / 256, 256>>>(
        part, (size_t)NN * OUTD, b2, h_out, OUTD / 4, Bhhi, Bhlo);

    // G5: out = sigmoid(h @ h^T)   A = h fp32 (in-kernel split), B = h frag
    tgemm<EPI_SIGMOID><<<dim3(NN / 128, NN / 128, 1), 256, SMEM_DYN>>>(
        h_out, Bhhi, Bhlo, out, NN, 0, OUTD, OUTD);
}